// round 3
// baseline (speedup 1.0000x reference)
#include <cuda_runtime.h>

#define B_   64
#define LX_  512
#define LY_  512
#define DIM_ 64
#define BIGF 1e30f

// Diagonal-major scratch: g_Dt[b][t][i] = D[b][i][t - i], t in [0, 1023)
__device__ float g_Dt[(size_t)B_ * 1024 * 512];

typedef unsigned long long u64;

__device__ __forceinline__ u64 pack2(float lo, float hi) {
    u64 r; asm("mov.b64 %0,{%1,%2};" : "=l"(r) : "f"(lo), "f"(hi)); return r;
}
__device__ __forceinline__ u64 ffma2(u64 a, u64 b, u64 c) {
    u64 d; asm("fma.rn.f32x2 %0,%1,%2,%3;" : "=l"(d) : "l"(a), "l"(b), "l"(c)); return d;
}
__device__ __forceinline__ float2 unpack2(u64 v) {
    float2 f; asm("mov.b64 {%0,%1},%2;" : "=f"(f.x), "=f"(f.y) : "l"(v)); return f;
}

#define TP 132            // smem pitch (floats) for k-major operand halves

// ---------------------------------------------------------------------------
// Kernel 1: batched pairwise squared-L2, 128x128 tiles, 256 threads,
// 8x8 micro-tiles, K split into two 32-wide halves, norms fused in k-loop,
// diagonal-major writeout per 64x64 quadrant.
// ---------------------------------------------------------------------------
__global__ __launch_bounds__(256) void sdtw_gemm_kernel(
    const float* __restrict__ X, const float* __restrict__ Y)
{
    __shared__ float pool[2 * 32 * TP];      // 33.8 KB
    float* Xs = pool;                        // [32][TP], k-major: Xs[k][i]
    float* Ys = pool + 32 * TP;              // [32][TP], k-major: Ys[k][j]

    const int b  = blockIdx.z;
    const int i0 = blockIdx.y * 128;
    const int j0 = blockIdx.x * 128;
    const int tid = threadIdx.x;
    const int tx = tid & 15;                 // j micro (cols tx*8..tx*8+7)
    const int ty = tid >> 4;                 // i micro (rows ty*8..ty*8+7)

    const float* Xb = X + ((size_t)b * LX_ + i0) * DIM_;
    const float* Yb = Y + ((size_t)b * LY_ + j0) * DIM_;

    u64 acc2[8][4];                          // acc2[r][p] = dot pairs
    u64 xn2[4], yn2[4];                      // packed row/col norms
    const u64 z = pack2(0.f, 0.f);
#pragma unroll
    for (int r = 0; r < 8; ++r)
#pragma unroll
        for (int p = 0; p < 4; ++p) acc2[r][p] = z;
#pragma unroll
    for (int p = 0; p < 4; ++p) { xn2[p] = z; yn2[p] = z; }

#pragma unroll 1
    for (int kh = 0; kh < 2; ++kh) {
        __syncthreads();                     // prior compute done reading smem
        // Load 128x32 halves of X and Y, transposed to k-major.
#pragma unroll
        for (int it = 0; it < 4; ++it) {
            int f4  = it * 256 + tid;        // 0..1023
            int row = f4 >> 3;               // 0..127
            int k4  = (f4 & 7) << 2;         // 0..28
            float4 xv = *(const float4*)(Xb + row * DIM_ + kh * 32 + k4);
            Xs[(k4 + 0) * TP + row] = xv.x; Xs[(k4 + 1) * TP + row] = xv.y;
            Xs[(k4 + 2) * TP + row] = xv.z; Xs[(k4 + 3) * TP + row] = xv.w;
            float4 yv = *(const float4*)(Yb + row * DIM_ + kh * 32 + k4);
            Ys[(k4 + 0) * TP + row] = yv.x; Ys[(k4 + 1) * TP + row] = yv.y;
            Ys[(k4 + 2) * TP + row] = yv.z; Ys[(k4 + 3) * TP + row] = yv.w;
        }
        __syncthreads();

#pragma unroll 8
        for (int k = 0; k < 32; ++k) {
            float4 xa = *(const float4*)&Xs[k * TP + ty * 8];
            float4 xb = *(const float4*)&Xs[k * TP + ty * 8 + 4];
            float4 ya = *(const float4*)&Ys[k * TP + tx * 8];
            float4 yb = *(const float4*)&Ys[k * TP + tx * 8 + 4];
            u64 yp[4] = { pack2(ya.x, ya.y), pack2(ya.z, ya.w),
                          pack2(yb.x, yb.y), pack2(yb.z, yb.w) };
            float xs[8] = {xa.x, xa.y, xa.z, xa.w, xb.x, xb.y, xb.z, xb.w};
#pragma unroll
            for (int r = 0; r < 8; ++r) {
                u64 xp = pack2(xs[r], xs[r]);
#pragma unroll
                for (int p = 0; p < 4; ++p)
                    acc2[r][p] = ffma2(xp, yp[p], acc2[r][p]);
            }
            u64 xq[4] = { pack2(xa.x, xa.y), pack2(xa.z, xa.w),
                          pack2(xb.x, xb.y), pack2(xb.z, xb.w) };
#pragma unroll
            for (int p = 0; p < 4; ++p) {
                xn2[p] = ffma2(xq[p], xq[p], xn2[p]);
                yn2[p] = ffma2(yp[p], yp[p], yn2[p]);
            }
        }
    }

    // d = x2 + y2 - 2*dot
    float xn[8], yn[8], dres[8][8];
#pragma unroll
    for (int p = 0; p < 4; ++p) {
        float2 xv = unpack2(xn2[p]); xn[2*p] = xv.x; xn[2*p+1] = xv.y;
        float2 yv = unpack2(yn2[p]); yn[2*p] = yv.x; yn[2*p+1] = yv.y;
    }
#pragma unroll
    for (int r = 0; r < 8; ++r)
#pragma unroll
        for (int p = 0; p < 4; ++p) {
            float2 a = unpack2(acc2[r][p]);
            dres[r][2*p]   = fmaf(-2.0f, a.x, xn[r] + yn[2*p]);
            dres[r][2*p+1] = fmaf(-2.0f, a.y, xn[r] + yn[2*p+1]);
        }

    // Writeout per 64x64 quadrant through reused smem (pitch 66 ->
    // anti-diagonal stride 65, conflict-free).
    const int CP = 66;
    float* stage = pool;                     // 4224 floats = 64*66 exactly
    const int g  = tid >> 6;
    const int li = tid & 63;
#pragma unroll 1
    for (int q = 0; q < 4; ++q) {
        int qi = q >> 1, qj = q & 1;
        __syncthreads();                     // prev drain done / smem free
        if ((ty >> 3) == qi && (tx >> 3) == qj) {
            int r0 = (ty & 7) * 8, c0 = (tx & 7) * 8;
#pragma unroll
            for (int r = 0; r < 8; ++r)
#pragma unroll
                for (int c = 0; c < 8; ++c)
                    stage[(r0 + r) * CP + (c0 + c)] = dres[r][c];
        }
        __syncthreads();
        int i0q = i0 + qi * 64, j0q = j0 + qj * 64;
        float* Dtb = g_Dt + (size_t)b * (1024 * 512)
                   + (size_t)(i0q + j0q) * 512 + i0q;
        for (int tl = g; tl < 127; tl += 4) {
            int ilo = tl - 63; if (ilo < 0) ilo = 0;
            int ihi = tl;      if (ihi > 63) ihi = 63;
            if (li >= ilo && li <= ihi)
                Dtb[(size_t)tl * 512 + li] = stage[li * (CP - 1) + tl];
        }
    }
}

// ---------------------------------------------------------------------------
// Kernel 2: soft-DTW wavefront. One CTA per batch, 128 threads, 4 rows per
// thread. 3/4 of the neighbor deps live in registers; one float2 smem
// exchange + one __syncthreads (4 warps) per diagonal. 3 MUFU per cell via
// sort3 (exp of the min == 1 exactly). float4 D loads, depth-4 static ring.
// ---------------------------------------------------------------------------
__global__ __launch_bounds__(128) void sdtw_dp_kernel(float* __restrict__ out)
{
    __shared__ float2 xch[2][129];

    const int k = threadIdx.x;               // 0..127
    const int b = blockIdx.x;
    const int base = k * 4;                  // first row owned by this thread
    const float* __restrict__ Db = g_Dt + (size_t)b * (1024 * 512) + base;

    xch[0][k + 1] = make_float2(BIGF, BIGF);
    xch[1][k + 1] = make_float2(BIGF, BIGF);
    if (k == 0) {
        xch[0][0] = make_float2(BIGF, BIGF);
        xch[1][0] = make_float2(BIGF, BIGF);
    }

    float a1[4], a2[4];                      // r1/r2 for my 4 rows
#pragma unroll
    for (int r = 0; r < 4; ++r) { a1[r] = BIGF; a2[r] = BIGF; }

    float4 dv[4];                            // prefetch ring, depth 4
#pragma unroll
    for (int u = 0; u < 4; ++u)
        dv[u] = *(const float4*)(Db + (size_t)u * 512);
    __syncthreads();

    const float L2E = 1.44269504f;
    const float LN2 = 0.69314718f;

#pragma unroll 1
    for (int tb = 0; tb < 1024; tb += 4) {
#pragma unroll
        for (int u = 0; u < 4; ++u) {
            int t = tb + u;
            if (t < 1023) {                  // uniform across CTA
                float4 dc = dv[u];
                int tp = t + 4; if (tp > 1022) tp = 1022;
                dv[u] = *(const float4*)(Db + (size_t)tp * 512);

                float2 nb = xch[(t + 1) & 1][k];   // neighbor row base-1
                float nu = nb.x;                   // r1[base-1]
                float nd = nb.y;                   // r2[base-1]
                if (k == 0 && t == 0) nd = 0.0f;   // soft-DTW origin

                float d[4] = {dc.x, dc.y, dc.z, dc.w};
                float rc[4];
#pragma unroll
                for (int r = 0; r < 4; ++r) {
                    float up = (r == 0) ? nu : a1[r - 1];
                    float dg = (r == 0) ? nd : a2[r - 1];
                    int j = t - (base + r);
                    float lf = (j >= 1) ? a1[r] : BIGF;

                    // sort3 -> softmin with exp(min-min)=1 folded out
                    float mn = fminf(up, dg), mx = fmaxf(up, dg);
                    float m  = fminf(mn, lf);
                    float md = fmaxf(mn, fminf(mx, lf));
                    float hi = fmaxf(mx, lf);
                    float mc = m * L2E;
                    float e1 = exp2f(fmaf(-L2E, md, mc));
                    float e2 = exp2f(fmaf(-L2E, hi, mc));
                    float s  = 1.0f + e1 + e2;
                    float smin = fmaf(-LN2, __log2f(s), m);

                    rc[r] = ((unsigned)j <= 511u) ? (d[r] + smin) : BIGF;
                }
#pragma unroll
                for (int r = 0; r < 4; ++r) { a2[r] = a1[r]; a1[r] = rc[r]; }

                xch[t & 1][k + 1] = make_float2(a1[3], a2[3]);
                __syncthreads();
            }
        }
    }

    if (k == 127) out[b] = a1[3];            // R[511][511]
}

// ---------------------------------------------------------------------------
extern "C" void kernel_launch(void* const* d_in, const int* in_sizes, int n_in,
                              void* d_out, int out_size)
{
    (void)in_sizes; (void)n_in; (void)out_size;
    const float* X = (const float*)d_in[0];
    const float* Y = (const float*)d_in[1];
    float* out = (float*)d_out;

    dim3 gg(LY_ / 128, LX_ / 128, B_);       // (4, 4, 64)
    sdtw_gemm_kernel<<<gg, 256>>>(X, Y);
    sdtw_dp_kernel<<<B_, 128>>>(out);
}

// round 4
// speedup vs baseline: 2.3070x; 2.3070x over previous
#include <cuda_runtime.h>

#define B_   64
#define LX_  512
#define LY_  512
#define DIM_ 64
#define BIGF 1e30f

// Diagonal-major scratch: g_Dt[b][t][i] = D[b][i][t - i], t in [0, 1023)
__device__ float g_Dt[(size_t)B_ * 1024 * 512];

typedef unsigned long long u64;

__device__ __forceinline__ u64 pack2(float lo, float hi) {
    u64 r; asm("mov.b64 %0,{%1,%2};" : "=l"(r) : "f"(lo), "f"(hi)); return r;
}
__device__ __forceinline__ u64 ffma2(u64 a, u64 b, u64 c) {
    u64 d; asm("fma.rn.f32x2 %0,%1,%2,%3;" : "=l"(d) : "l"(a), "l"(b), "l"(c)); return d;
}
__device__ __forceinline__ float2 unpack2(u64 v) {
    float2 f; asm("mov.b64 {%0,%1},%2;" : "=f"(f.x), "=f"(f.y) : "l"(v)); return f;
}

#define TP 132

// ---------------------------------------------------------------------------
// Kernel 1: batched pairwise squared-L2, 128x128 tiles, 256 threads,
// 8x8 micro-tiles, diagonal-major writeout (unchanged from R3).
// ---------------------------------------------------------------------------
__global__ __launch_bounds__(256) void sdtw_gemm_kernel(
    const float* __restrict__ X, const float* __restrict__ Y)
{
    __shared__ float pool[2 * 32 * TP];
    float* Xs = pool;
    float* Ys = pool + 32 * TP;

    const int b  = blockIdx.z;
    const int i0 = blockIdx.y * 128;
    const int j0 = blockIdx.x * 128;
    const int tid = threadIdx.x;
    const int tx = tid & 15;
    const int ty = tid >> 4;

    const float* Xb = X + ((size_t)b * LX_ + i0) * DIM_;
    const float* Yb = Y + ((size_t)b * LY_ + j0) * DIM_;

    u64 acc2[8][4];
    u64 xn2[4], yn2[4];
    const u64 z = pack2(0.f, 0.f);
#pragma unroll
    for (int r = 0; r < 8; ++r)
#pragma unroll
        for (int p = 0; p < 4; ++p) acc2[r][p] = z;
#pragma unroll
    for (int p = 0; p < 4; ++p) { xn2[p] = z; yn2[p] = z; }

#pragma unroll 1
    for (int kh = 0; kh < 2; ++kh) {
        __syncthreads();
#pragma unroll
        for (int it = 0; it < 4; ++it) {
            int f4  = it * 256 + tid;
            int row = f4 >> 3;
            int k4  = (f4 & 7) << 2;
            float4 xv = *(const float4*)(Xb + row * DIM_ + kh * 32 + k4);
            Xs[(k4 + 0) * TP + row] = xv.x; Xs[(k4 + 1) * TP + row] = xv.y;
            Xs[(k4 + 2) * TP + row] = xv.z; Xs[(k4 + 3) * TP + row] = xv.w;
            float4 yv = *(const float4*)(Yb + row * DIM_ + kh * 32 + k4);
            Ys[(k4 + 0) * TP + row] = yv.x; Ys[(k4 + 1) * TP + row] = yv.y;
            Ys[(k4 + 2) * TP + row] = yv.z; Ys[(k4 + 3) * TP + row] = yv.w;
        }
        __syncthreads();

#pragma unroll 8
        for (int k = 0; k < 32; ++k) {
            float4 xa = *(const float4*)&Xs[k * TP + ty * 8];
            float4 xb = *(const float4*)&Xs[k * TP + ty * 8 + 4];
            float4 ya = *(const float4*)&Ys[k * TP + tx * 8];
            float4 yb = *(const float4*)&Ys[k * TP + tx * 8 + 4];
            u64 yp[4] = { pack2(ya.x, ya.y), pack2(ya.z, ya.w),
                          pack2(yb.x, yb.y), pack2(yb.z, yb.w) };
            float xs[8] = {xa.x, xa.y, xa.z, xa.w, xb.x, xb.y, xb.z, xb.w};
#pragma unroll
            for (int r = 0; r < 8; ++r) {
                u64 xp = pack2(xs[r], xs[r]);
#pragma unroll
                for (int p = 0; p < 4; ++p)
                    acc2[r][p] = ffma2(xp, yp[p], acc2[r][p]);
            }
            u64 xq[4] = { pack2(xa.x, xa.y), pack2(xa.z, xa.w),
                          pack2(xb.x, xb.y), pack2(xb.z, xb.w) };
#pragma unroll
            for (int p = 0; p < 4; ++p) {
                xn2[p] = ffma2(xq[p], xq[p], xn2[p]);
                yn2[p] = ffma2(yp[p], yp[p], yn2[p]);
            }
        }
    }

    float xn[8], yn[8], dres[8][8];
#pragma unroll
    for (int p = 0; p < 4; ++p) {
        float2 xv = unpack2(xn2[p]); xn[2*p] = xv.x; xn[2*p+1] = xv.y;
        float2 yv = unpack2(yn2[p]); yn[2*p] = yv.x; yn[2*p+1] = yv.y;
    }
#pragma unroll
    for (int r = 0; r < 8; ++r)
#pragma unroll
        for (int p = 0; p < 4; ++p) {
            float2 a = unpack2(acc2[r][p]);
            dres[r][2*p]   = fmaf(-2.0f, a.x, xn[r] + yn[2*p]);
            dres[r][2*p+1] = fmaf(-2.0f, a.y, xn[r] + yn[2*p+1]);
        }

    const int CP = 66;
    float* stage = pool;
    const int g  = tid >> 6;
    const int li = tid & 63;
#pragma unroll 1
    for (int q = 0; q < 4; ++q) {
        int qi = q >> 1, qj = q & 1;
        __syncthreads();
        if ((ty >> 3) == qi && (tx >> 3) == qj) {
            int r0 = (ty & 7) * 8, c0 = (tx & 7) * 8;
#pragma unroll
            for (int r = 0; r < 8; ++r)
#pragma unroll
                for (int c = 0; c < 8; ++c)
                    stage[(r0 + r) * CP + (c0 + c)] = dres[r][c];
        }
        __syncthreads();
        int i0q = i0 + qi * 64, j0q = j0 + qj * 64;
        float* Dtb = g_Dt + (size_t)b * (1024 * 512)
                   + (size_t)(i0q + j0q) * 512 + i0q;
        for (int tl = g; tl < 127; tl += 4) {
            int ilo = tl - 63; if (ilo < 0) ilo = 0;
            int ihi = tl;      if (ihi > 63) ihi = 63;
            if (li >= ilo && li <= ihi)
                Dtb[(size_t)tl * 512 + li] = stage[li * (CP - 1) + tl];
        }
    }
}

// ---------------------------------------------------------------------------
// Kernel 2: warp-pipelined soft-DTW wavefront.
// One CTA/batch, 16 warps. Warp w = rows [32w,32w+32), lane l = row 32w+l,
// skewed: at local step s lane l computes (32w+l, s-l). Neighbor deps via
// two shfl_up (register pipeline). Cross-warp boundary row via smem,
// chunked C=16 steps, producer lag L=3 chunks -> 79 barriers total.
// ---------------------------------------------------------------------------
__global__ __launch_bounds__(512) void sdtw_dp_kernel(float* __restrict__ out)
{
    __shared__ float bnd[16][520];   // bnd[w][c+1] = R[32w+31][c]; [w][0]=BIG

    const int tid = threadIdx.x;
    const int w = tid >> 5;
    const int l = tid & 31;
    const int b = blockIdx.x;

    if (l == 0) bnd[w][0] = BIGF;

    // DW[s*512] = Dt[b][32w+s][32w+l]
    const float* __restrict__ DW =
        g_Dt + (size_t)b * (1024 * 512) + (size_t)(32 * w) * 512 + 32 * w + l;

    float a1 = BIGF, a2 = BIGF;      // R[i][j-1], R[i][j-2] for my row i
    float dring[8];
#pragma unroll
    for (int u = 0; u < 8; ++u) dring[u] = __ldg(DW + (size_t)u * 512);

    __syncthreads();

    const float L2E = 1.44269504f;
    const float LN2 = 0.69314718f;
    const int NCH = 34;              // ceil(543/16)
    const int LAG = 3;
    const int P = 15 * LAG + NCH;    // 79 phases
    const float* bprev = bnd[(w > 0) ? (w - 1) : 0];

#pragma unroll 1
    for (int p = 0; p < P; ++p) {
        int q = p - LAG * w;
        if (q >= 0 && q < NCH) {
            int s0 = q * 16;
#pragma unroll
            for (int u = 0; u < 16; ++u) {
                int s = s0 + u;
                if (s < 543) {                       // warp-uniform
                    float d = dring[u & 7];
                    int sp = s + 8; if (sp > 542) sp = 542;
                    dring[u & 7] = __ldg(DW + (size_t)sp * 512);

                    float up = __shfl_up_sync(0xFFFFFFFFu, a1, 1);
                    float dg = __shfl_up_sync(0xFFFFFFFFu, a2, 1);
                    int j = s - l;
                    if (l == 0) {
                        if (w == 0) {
                            up = BIGF;
                            dg = (s == 0) ? 0.0f : BIGF;
                        } else {
                            int jc = (j > 511) ? 511 : j;
                            up = bprev[jc + 1];      // R[32w-1][j]
                            dg = bprev[jc];          // R[32w-1][j-1]
                        }
                    }
                    float lf = (j >= 1) ? a1 : BIGF;

                    // softmin via sort3 (exp of the min folded to 1)
                    float mn = fminf(up, dg), mx = fmaxf(up, dg);
                    float m  = fminf(mn, lf);
                    float md = fmaxf(mn, fminf(mx, lf));
                    float hi = fmaxf(mx, lf);
                    float mc = m * L2E;
                    float e1 = exp2f(fmaf(-L2E, md, mc));
                    float e2 = exp2f(fmaf(-L2E, hi, mc));
                    float smin = fmaf(-LN2, __log2f(1.0f + e1 + e2), m);

                    float rc = ((unsigned)j <= 511u) ? (d + smin) : BIGF;
                    a2 = a1; a1 = rc;

                    if (l == 31 && j >= 0)
                        bnd[w][j + 1] = rc;          // publish bottom row
                }
            }
        }
        __syncthreads();
    }

    if (w == 15 && l == 31) out[b] = a1;             // R[511][511]
}

// ---------------------------------------------------------------------------
extern "C" void kernel_launch(void* const* d_in, const int* in_sizes, int n_in,
                              void* d_out, int out_size)
{
    (void)in_sizes; (void)n_in; (void)out_size;
    const float* X = (const float*)d_in[0];
    const float* Y = (const float*)d_in[1];
    float* out = (float*)d_out;

    dim3 gg(LY_ / 128, LX_ / 128, B_);
    sdtw_gemm_kernel<<<gg, 256>>>(X, Y);
    sdtw_dp_kernel<<<B_, 512>>>(out);
}